// round 1
// baseline (speedup 1.0000x reference)
#include <cuda_runtime.h>

#define DDEPTH 8
#define HDIM   4096
#define NTHREADS 1024
#define NWARPS  (NTHREADS / 32)
#define EPSV    1e-6f

// smem layout (floats):
//   sv  [DDEPTH * HDIM]        = 32768 floats (128 KiB)  staged values tile
//   red [NWARPS * 16]          = 512 floats              per-warp partials
//   fin [16]                                             final reduced sums
#define SMEM_FLOATS (DDEPTH * HDIM + NWARPS * 16 + 16)

__global__ __launch_bounds__(NTHREADS, 1)
void fullattnres_kernel(const float* __restrict__ values,
                        const float* __restrict__ query,
                        const float* __restrict__ weight,
                        float* __restrict__ out,
                        int SB)   // S*B = number of sites
{
    extern __shared__ float smem[];
    float* sv  = smem;                       // [DDEPTH][HDIM]
    float* red = smem + DDEPTH * HDIM;       // [NWARPS][16]
    float* fin = red + NWARPS * 16;          // [16]

    const int tid  = threadIdx.x;
    const int lane = tid & 31;
    const int warp = tid >> 5;
    const int sb   = blockIdx.x;
    const int h    = tid * 4;                // 1024 threads * 4 = 4096 = HDIM

    const size_t base    = (size_t)sb * HDIM;
    const size_t dstride = (size_t)SB * HDIM;

    // q*w fused key weights for this thread's 4 hidden dims (L2-resident)
    const float4 q = *(const float4*)(query + h);
    const float4 w = *(const float4*)(weight + h);
    const float4 qw = make_float4(q.x * w.x, q.y * w.y, q.z * w.z, q.w * w.w);

    // Single global read pass: stage to smem + accumulate per-depth sums
    float ss[DDEPTH];   // sum of squares
    float dp[DDEPTH];   // dot(q*w, v)
    #pragma unroll
    for (int d = 0; d < DDEPTH; d++) {
        const float4 v = *(const float4*)(values + base + (size_t)d * dstride + h);
        *(float4*)(sv + d * HDIM + h) = v;
        ss[d] = v.x * v.x + v.y * v.y + v.z * v.z + v.w * v.w;
        dp[d] = qw.x * v.x + qw.y * v.y + qw.z * v.z + qw.w * v.w;
    }

    // Warp reduction of 16 scalars
    #pragma unroll
    for (int off = 16; off > 0; off >>= 1) {
        #pragma unroll
        for (int d = 0; d < DDEPTH; d++) {
            ss[d] += __shfl_xor_sync(0xFFFFFFFFu, ss[d], off);
            dp[d] += __shfl_xor_sync(0xFFFFFFFFu, dp[d], off);
        }
    }
    if (lane == 0) {
        #pragma unroll
        for (int d = 0; d < DDEPTH; d++) {
            red[warp * 16 + d]     = ss[d];
            red[warp * 16 + 8 + d] = dp[d];
        }
    }
    __syncthreads();

    // Cross-warp reduction: 16 threads each own one scalar
    if (tid < 16) {
        float s = 0.f;
        #pragma unroll
        for (int wp = 0; wp < NWARPS; wp++) s += red[wp * 16 + tid];
        fin[tid] = s;
    }
    __syncthreads();

    // Softmax over depth (computed redundantly by every thread; 8 values)
    float wt[DDEPTH];
    float mx = -3.402823466e38f;
    #pragma unroll
    for (int d = 0; d < DDEPTH; d++) {
        const float var   = fin[d] * (1.0f / HDIM);
        const float logit = fin[8 + d] * rsqrtf(var + EPSV);
        wt[d] = logit;
        mx = fmaxf(mx, logit);
    }
    float sum = 0.f;
    #pragma unroll
    for (int d = 0; d < DDEPTH; d++) {
        wt[d] = __expf(wt[d] - mx);
        sum += wt[d];
    }
    const float inv = 1.0f / sum;

    // Weighted combine from the smem tile, one float4 store per thread
    float4 o = make_float4(0.f, 0.f, 0.f, 0.f);
    #pragma unroll
    for (int d = 0; d < DDEPTH; d++) {
        const float wd = wt[d] * inv;
        const float4 v = *(const float4*)(sv + d * HDIM + h);
        o.x += wd * v.x;
        o.y += wd * v.y;
        o.z += wd * v.z;
        o.w += wd * v.w;
    }
    *(float4*)(out + base + h) = o;
}

extern "C" void kernel_launch(void* const* d_in, const int* in_sizes, int n_in,
                              void* d_out, int out_size)
{
    const float* values = (const float*)d_in[0];  // [D,S,B,H]
    const float* query  = (const float*)d_in[1];  // [H]
    const float* weight = (const float*)d_in[2];  // [H]
    float* out = (float*)d_out;                   // [S,B,H]

    const int H  = in_sizes[1];                   // 4096
    const int SB = out_size / H;                  // S*B = 4096

    const size_t smem_bytes = SMEM_FLOATS * sizeof(float);  // ~133 KiB
    // Idempotent, deterministic; not a stream op so safe under graph capture.
    cudaFuncSetAttribute(fullattnres_kernel,
                         cudaFuncAttributeMaxDynamicSharedMemorySize,
                         (int)smem_bytes);

    fullattnres_kernel<<<SB, NTHREADS, smem_bytes>>>(values, query, weight, out, SB);
}

// round 3
// speedup vs baseline: 1.0659x; 1.0659x over previous
#include <cuda_runtime.h>

#define DDEPTH 8
#define HDIM   4096
#define NT     512
#define NWARP  (NT / 32)
#define EPSV   1e-6f

// Each thread owns 8 contiguous hidden dims (512 thr * 8 = 4096 = HDIM).
// Depth-sequential online softmax: no values tile in smem at all.
__global__ __launch_bounds__(NT, 2)
void fullattnres_kernel(const float* __restrict__ values,
                        const float* __restrict__ query,
                        const float* __restrict__ weight,
                        float* __restrict__ out,
                        int SB)
{
    // double-buffered reduction scratch: [parity][0..15]=ss, [16..31]=dp
    __shared__ float red[2][2 * NWARP];

    const int tid  = threadIdx.x;
    const int lane = tid & 31;
    const int warp = tid >> 5;
    const int h    = tid * 8;

    const size_t base = (size_t)blockIdx.x * HDIM + h;
    const size_t dstr = (size_t)SB * HDIM;
    const float* p    = values + base;

    // fused q*w for this thread's 8 dims (L2-resident)
    const float4 q0 = *(const float4*)(query + h);
    const float4 q1 = *(const float4*)(query + h + 4);
    const float4 w0 = *(const float4*)(weight + h);
    const float4 w1 = *(const float4*)(weight + h + 4);
    const float4 qw0 = make_float4(q0.x*w0.x, q0.y*w0.y, q0.z*w0.z, q0.w*w0.w);
    const float4 qw1 = make_float4(q1.x*w1.x, q1.y*w1.y, q1.z*w1.z, q1.w*w1.w);

    // preload depth 0
    float4 va0 = *(const float4*)(p);
    float4 va1 = *(const float4*)(p + 4);

    float  m = -3.402823466e38f;
    float  s = 0.f;
    float4 acc0 = make_float4(0.f, 0.f, 0.f, 0.f);
    float4 acc1 = make_float4(0.f, 0.f, 0.f, 0.f);

    #pragma unroll
    for (int d = 0; d < DDEPTH; d++) {
        // partial sums for current depth
        float ss = va0.x*va0.x + va0.y*va0.y + va0.z*va0.z + va0.w*va0.w
                 + va1.x*va1.x + va1.y*va1.y + va1.z*va1.z + va1.w*va1.w;
        float dp = qw0.x*va0.x + qw0.y*va0.y + qw0.z*va0.z + qw0.w*va0.w
                 + qw1.x*va1.x + qw1.y*va1.y + qw1.z*va1.z + qw1.w*va1.w;

        // prefetch next depth BEFORE the reduce barrier (hides DRAM latency)
        float4 vb0, vb1;
        if (d < DDEPTH - 1) {
            const float* pn = p + (size_t)(d + 1) * dstr;
            vb0 = *(const float4*)(pn);
            vb1 = *(const float4*)(pn + 4);
        }

        // warp butterfly reduce
        #pragma unroll
        for (int off = 16; off > 0; off >>= 1) {
            ss += __shfl_xor_sync(0xFFFFFFFFu, ss, off);
            dp += __shfl_xor_sync(0xFFFFFFFFu, dp, off);
        }
        if (lane == 0) {
            red[d & 1][warp]         = ss;
            red[d & 1][NWARP + warp] = dp;
        }
        __syncthreads();   // single barrier per depth (parity buffers avoid WAR)

        // every thread redundantly reduces the 16 warp partials (broadcast LDS)
        float sst = 0.f, dpt = 0.f;
        #pragma unroll
        for (int w2 = 0; w2 < NWARP; w2++) {
            sst += red[d & 1][w2];
            dpt += red[d & 1][NWARP + w2];
        }
        const float l = dpt * rsqrtf(sst * (1.0f / HDIM) + EPSV);

        // online softmax update
        const float mn = fmaxf(m, l);
        const float cs = __expf(m - mn);   // d==0: exp(-inf)=0, acc is 0 anyway
        const float e  = __expf(l - mn);
        s = s * cs + e;
        acc0.x = acc0.x * cs + e * va0.x;
        acc0.y = acc0.y * cs + e * va0.y;
        acc0.z = acc0.z * cs + e * va0.z;
        acc0.w = acc0.w * cs + e * va0.w;
        acc1.x = acc1.x * cs + e * va1.x;
        acc1.y = acc1.y * cs + e * va1.y;
        acc1.z = acc1.z * cs + e * va1.z;
        acc1.w = acc1.w * cs + e * va1.w;
        m = mn;

        va0 = vb0;
        va1 = vb1;
    }

    const float inv = 1.0f / s;
    float4 o0 = make_float4(acc0.x * inv, acc0.y * inv, acc0.z * inv, acc0.w * inv);
    float4 o1 = make_float4(acc1.x * inv, acc1.y * inv, acc1.z * inv, acc1.w * inv);
    *(float4*)(out + base)     = o0;
    *(float4*)(out + base + 4) = o1;
}

extern "C" void kernel_launch(void* const* d_in, const int* in_sizes, int n_in,
                              void* d_out, int out_size)
{
    const float* values = (const float*)d_in[0];  // [D,S,B,H]
    const float* query  = (const float*)d_in[1];  // [H]
    const float* weight = (const float*)d_in[2];  // [H]
    float* out = (float*)d_out;                   // [S,B,H]

    const int H  = in_sizes[1];                   // 4096
    const int SB = out_size / H;                  // S*B = 4096

    fullattnres_kernel<<<SB, NT>>>(values, query, weight, out, SB);
}